// round 1
// baseline (speedup 1.0000x reference)
#include <cuda_runtime.h>
#include <math.h>

// Problem constants (fixed shapes from reference)
#define TT    4
#define BB    64
#define CC    384
#define NN    196
#define NHEAD 8
#define DHD   48
#define CN    (CC*NN)          // 75264
#define BCN   (BB*CC*NN)       // 4816896
#define TBCN  (TT*BCN)         // 19267584
#define BHN   (BB*NHEAD*NN)    // 100352

// Scratch (allocation-free: __device__ globals)
__device__ float         g_pre[2u*TBCN];   // [0]=q pre / later p pre, [1]=k pre
__device__ unsigned char g_qs[TBCN];
__device__ unsigned char g_ks[TBCN];
__device__ unsigned char g_attn[TT*BHN];
__device__ float         g_scale[3*CC];

// ---------------------------------------------------------------------------
__global__ void bn_precompute(const float* __restrict__ qg, const float* __restrict__ qv,
                              const float* __restrict__ kg, const float* __restrict__ kv,
                              const float* __restrict__ pg, const float* __restrict__ pv)
{
    int c = threadIdx.x;
    if (c < CC) {
        g_scale[c]        = qg[c] / sqrtf(qv[c] + 1e-5f);
        g_scale[CC + c]   = kg[c] / sqrtf(kv[c] + 1e-5f);
        g_scale[2*CC + c] = pg[c] / sqrtf(pv[c] + 1e-5f);
    }
}

// ---------------------------------------------------------------------------
// Batched fp32 GEMM for q and k, fused over M (rows 0..383 = Wq, 384..767 = Wk).
// Per batch z = t*BB+b: out[m,n] = sum_c W[m,c] * x[z,c,n]; BN epilogue.
// Block: 64 (M) x 196 (full N). Threads (28,8): per-thread 8x7 register tile.
__global__ __launch_bounds__(224) void gemm_qk(
    const float* __restrict__ x,
    const float* __restrict__ Wq, const float* __restrict__ Wk,
    const float* __restrict__ qbeta, const float* __restrict__ qmean,
    const float* __restrict__ kbeta, const float* __restrict__ kmean)
{
    __shared__ float Ws[64][17];    // [m][k], padded
    __shared__ float Xs[16][200];   // [k][n], padded

    const int z     = blockIdx.x;          // t*BB + b
    const int mt    = blockIdx.y;          // 0..11
    const int sel   = (mt >= 6) ? 1 : 0;   // 0 = q, 1 = k
    const int mbase = (mt - sel*6) * 64;

    const float* __restrict__ W    = sel ? Wk    : Wq;
    const float* __restrict__ beta = sel ? kbeta : qbeta;
    const float* __restrict__ mean = sel ? kmean : qmean;
    const float* __restrict__ scl  = g_scale + sel*CC;

    const int tx  = threadIdx.x;   // 0..27 (n)
    const int ty  = threadIdx.y;   // 0..7  (m)
    const int tid = ty*28 + tx;

    const float* __restrict__ xb = x + (size_t)z * CN;

    float acc[8][7];
    #pragma unroll
    for (int i = 0; i < 8; i++)
        #pragma unroll
        for (int j = 0; j < 7; j++) acc[i][j] = 0.f;

    float wreg[5];
    float xreg[14];

    // prefetch first K-chunk
    #pragma unroll
    for (int u = 0; u < 5; u++) {
        int idx = tid + u*224;
        if (idx < 1024) {
            int r = idx >> 4, c = idx & 15;
            wreg[u] = W[(mbase + r)*CC + c];
        }
    }
    #pragma unroll
    for (int u = 0; u < 14; u++) {
        int idx = tid + u*224;
        int c = idx / NN, n = idx - c*NN;
        xreg[u] = xb[c*NN + n];
    }

    for (int k0 = 0; k0 < CC; k0 += 16) {
        // commit prefetched tile
        #pragma unroll
        for (int u = 0; u < 5; u++) {
            int idx = tid + u*224;
            if (idx < 1024) {
                int r = idx >> 4, c = idx & 15;
                Ws[r][c] = wreg[u];
            }
        }
        #pragma unroll
        for (int u = 0; u < 14; u++) {
            int idx = tid + u*224;
            int c = idx / NN, n = idx - c*NN;
            Xs[c][n] = xreg[u];
        }
        __syncthreads();

        // prefetch next chunk (overlaps with compute)
        const int k1 = k0 + 16;
        if (k1 < CC) {
            #pragma unroll
            for (int u = 0; u < 5; u++) {
                int idx = tid + u*224;
                if (idx < 1024) {
                    int r = idx >> 4, c = idx & 15;
                    wreg[u] = W[(mbase + r)*CC + k1 + c];
                }
            }
            #pragma unroll
            for (int u = 0; u < 14; u++) {
                int idx = tid + u*224;
                int c = idx / NN, n = idx - c*NN;
                xreg[u] = xb[(k1 + c)*NN + n];
            }
        }

        #pragma unroll
        for (int kk = 0; kk < 16; kk++) {
            float wv[8], xv[7];
            #pragma unroll
            for (int i = 0; i < 8; i++) wv[i] = Ws[ty*8 + i][kk];
            #pragma unroll
            for (int j = 0; j < 7; j++) xv[j] = Xs[kk][tx + 28*j];
            #pragma unroll
            for (int i = 0; i < 8; i++)
                #pragma unroll
                for (int j = 0; j < 7; j++)
                    acc[i][j] = fmaf(wv[i], xv[j], acc[i][j]);
        }
        __syncthreads();
    }

    float* __restrict__ outp = g_pre + (size_t)sel*TBCN + (size_t)z*CN;
    #pragma unroll
    for (int i = 0; i < 8; i++) {
        int ch = mbase + ty*8 + i;
        float sc = scl[ch], mu = mean[ch], be = beta[ch];
        #pragma unroll
        for (int j = 0; j < 7; j++) {
            int n = tx + 28*j;
            outp[ch*NN + n] = (acc[i][j] - mu)*sc + be;
        }
    }
}

// ---------------------------------------------------------------------------
// LIF over T for q and k pre-activations -> binary spikes (u8)
__global__ void lif_qk()
{
    int i = blockIdx.x*blockDim.x + threadIdx.x;
    if (i >= BCN) return;
    float vq = 0.f, vk = 0.f;
    #pragma unroll
    for (int t = 0; t < TT; t++) {
        float xq = g_pre[(size_t)t*BCN + i];
        vq = vq + (xq - vq)*0.5f;
        unsigned char sq = (vq >= 1.0f) ? 1 : 0;
        g_qs[(size_t)t*BCN + i] = sq;
        if (sq) vq = 0.f;

        float xk = g_pre[(size_t)TBCN + (size_t)t*BCN + i];
        vk = vk + (xk - vk)*0.5f;
        unsigned char sk = (vk >= 1.0f) ? 1 : 0;
        g_ks[(size_t)t*BCN + i] = sk;
        if (sk) vk = 0.f;
    }
}

// ---------------------------------------------------------------------------
// Per-head sum of q spikes (48 channels) + LIF over T -> attn mask (u8)
__global__ void attn_kernel()
{
    int idx = blockIdx.x*blockDim.x + threadIdx.x;
    if (idx >= BHN) return;
    int n = idx % NN;
    int h = (idx / NN) % NHEAD;
    int b = idx / (NN*NHEAD);

    float v = 0.f;
    #pragma unroll
    for (int t = 0; t < TT; t++) {
        const unsigned char* __restrict__ p =
            g_qs + ((size_t)(t*BB + b)*CC + h*DHD)*NN + n;
        int s = 0;
        #pragma unroll
        for (int i2 = 0; i2 < DHD; i2++) s += p[(size_t)i2*NN];
        float sf = (float)s;
        v = v + (sf - v)*0.5f;
        unsigned char a = (v >= 1.0f) ? 1 : 0;
        g_attn[((size_t)(t*BB + b)*NHEAD + h)*NN + n] = a;
        if (a) v = 0.f;
    }
}

// ---------------------------------------------------------------------------
// GEMM Wp @ (attn & k) + bias, BN epilogue. Operand built on the fly (binary).
__global__ __launch_bounds__(224) void gemm_p(
    const float* __restrict__ Wp, const float* __restrict__ bp,
    const float* __restrict__ pbeta, const float* __restrict__ pmean)
{
    __shared__ float Ws[64][17];
    __shared__ float Xs[16][200];

    const int z     = blockIdx.x;
    const int mt    = blockIdx.y;       // 0..5
    const int mbase = mt * 64;
    const float* __restrict__ scl = g_scale + 2*CC;

    const int tx  = threadIdx.x;
    const int ty  = threadIdx.y;
    const int tid = ty*28 + tx;

    const unsigned char* __restrict__ kb = g_ks   + (size_t)z*CN;
    const unsigned char* __restrict__ ab = g_attn + (size_t)z*NHEAD*NN;

    float acc[8][7];
    #pragma unroll
    for (int i = 0; i < 8; i++)
        #pragma unroll
        for (int j = 0; j < 7; j++) acc[i][j] = 0.f;

    float wreg[5];
    float xreg[14];

    #pragma unroll
    for (int u = 0; u < 5; u++) {
        int idx = tid + u*224;
        if (idx < 1024) {
            int r = idx >> 4, c = idx & 15;
            wreg[u] = Wp[(mbase + r)*CC + c];
        }
    }
    #pragma unroll
    for (int u = 0; u < 14; u++) {
        int idx = tid + u*224;
        int c = idx / NN, n = idx - c*NN;
        xreg[u] = (kb[c*NN + n] & ab[(c/DHD)*NN + n]) ? 1.f : 0.f;
    }

    for (int k0 = 0; k0 < CC; k0 += 16) {
        #pragma unroll
        for (int u = 0; u < 5; u++) {
            int idx = tid + u*224;
            if (idx < 1024) {
                int r = idx >> 4, c = idx & 15;
                Ws[r][c] = wreg[u];
            }
        }
        #pragma unroll
        for (int u = 0; u < 14; u++) {
            int idx = tid + u*224;
            int c = idx / NN, n = idx - c*NN;
            Xs[c][n] = xreg[u];
        }
        __syncthreads();

        const int k1 = k0 + 16;
        if (k1 < CC) {
            #pragma unroll
            for (int u = 0; u < 5; u++) {
                int idx = tid + u*224;
                if (idx < 1024) {
                    int r = idx >> 4, c = idx & 15;
                    wreg[u] = Wp[(mbase + r)*CC + k1 + c];
                }
            }
            #pragma unroll
            for (int u = 0; u < 14; u++) {
                int idx = tid + u*224;
                int c = idx / NN, n = idx - c*NN;
                int cg = k1 + c;
                xreg[u] = (kb[cg*NN + n] & ab[(cg/DHD)*NN + n]) ? 1.f : 0.f;
            }
        }

        #pragma unroll
        for (int kk = 0; kk < 16; kk++) {
            float wv[8], xv[7];
            #pragma unroll
            for (int i = 0; i < 8; i++) wv[i] = Ws[ty*8 + i][kk];
            #pragma unroll
            for (int j = 0; j < 7; j++) xv[j] = Xs[kk][tx + 28*j];
            #pragma unroll
            for (int i = 0; i < 8; i++)
                #pragma unroll
                for (int j = 0; j < 7; j++)
                    acc[i][j] = fmaf(wv[i], xv[j], acc[i][j]);
        }
        __syncthreads();
    }

    float* __restrict__ outp = g_pre + (size_t)z*CN;   // reuse q region
    #pragma unroll
    for (int i = 0; i < 8; i++) {
        int ch = mbase + ty*8 + i;
        float sc = scl[ch], mu = pmean[ch], be = pbeta[ch], bv = bp[ch];
        #pragma unroll
        for (int j = 0; j < 7; j++) {
            int n = tx + 28*j;
            float tmp = acc[i][j] + bv;          // conv bias first (match ref)
            outp[ch*NN + n] = (tmp - mu)*sc + be;
        }
    }
}

// ---------------------------------------------------------------------------
// Final LIF over T -> binary output (float 0/1)
__global__ void lif_out(float* __restrict__ out)
{
    int i = blockIdx.x*blockDim.x + threadIdx.x;
    if (i >= BCN) return;
    float v = 0.f;
    #pragma unroll
    for (int t = 0; t < TT; t++) {
        float xp = g_pre[(size_t)t*BCN + i];
        v = v + (xp - v)*0.5f;
        float s = (v >= 1.0f) ? 1.0f : 0.0f;
        out[(size_t)t*BCN + i] = s;
        if (s != 0.0f) v = 0.f;
    }
}

// ---------------------------------------------------------------------------
extern "C" void kernel_launch(void* const* d_in, const int* in_sizes, int n_in,
                              void* d_out, int out_size)
{
    const float* x   = (const float*)d_in[0];
    const float* Wq  = (const float*)d_in[1];
    const float* qg  = (const float*)d_in[2];
    const float* qb  = (const float*)d_in[3];
    const float* qm  = (const float*)d_in[4];
    const float* qv  = (const float*)d_in[5];
    const float* Wk  = (const float*)d_in[6];
    const float* kg  = (const float*)d_in[7];
    const float* kb  = (const float*)d_in[8];
    const float* km  = (const float*)d_in[9];
    const float* kv  = (const float*)d_in[10];
    const float* Wp  = (const float*)d_in[11];
    const float* bp  = (const float*)d_in[12];
    const float* pg  = (const float*)d_in[13];
    const float* pb  = (const float*)d_in[14];
    const float* pm  = (const float*)d_in[15];
    const float* pv  = (const float*)d_in[16];
    float* out = (float*)d_out;

    bn_precompute<<<1, CC>>>(qg, qv, kg, kv, pg, pv);
    gemm_qk<<<dim3(TT*BB, 12), dim3(28, 8)>>>(x, Wq, Wk, qb, qm, kb, km);
    lif_qk<<<(BCN + 255)/256, 256>>>();
    attn_kernel<<<(BHN + 255)/256, 256>>>();
    gemm_p<<<dim3(TT*BB, 6), dim3(28, 8)>>>(Wp, bp, pb, pm);
    lif_out<<<(BCN + 255)/256, 256>>>(out);
}

// round 2
// speedup vs baseline: 1.0331x; 1.0331x over previous
#include <cuda_runtime.h>
#include <math.h>

// Problem constants (fixed shapes from reference)
#define TT    4
#define BB    64
#define CC    384
#define NN    196
#define NHEAD 8
#define DHD   48
#define CN    (CC*NN)          // 75264
#define BCN   (BB*CC*NN)       // 4816896
#define TBCN  (TT*BCN)         // 19267584
#define BHN   (BB*NHEAD*NN)    // 100352

#define BMQ   128              // M tile
#define WS_S  132              // Ws row stride (m-dim, padded)
#define XS_S  200              // Xs row stride (n-dim, padded)

// Scratch (allocation-free: __device__ globals)
__device__ float         g_pre[2u*TBCN];   // [0]=q pre / later p pre, [1]=k pre
__device__ unsigned char g_qs[TBCN];
__device__ unsigned char g_ks[TBCN];
__device__ unsigned char g_attn[TT*BHN];
__device__ float         g_scale[3*CC];

// ---------------------------------------------------------------------------
__global__ void bn_precompute(const float* __restrict__ qg, const float* __restrict__ qv,
                              const float* __restrict__ kg, const float* __restrict__ kv,
                              const float* __restrict__ pg, const float* __restrict__ pv)
{
    int c = threadIdx.x;
    if (c < CC) {
        g_scale[c]        = qg[c] / sqrtf(qv[c] + 1e-5f);
        g_scale[CC + c]   = kg[c] / sqrtf(kv[c] + 1e-5f);
        g_scale[2*CC + c] = pg[c] / sqrtf(pv[c] + 1e-5f);
    }
}

// ---------------------------------------------------------------------------
// Batched fp32 GEMM for q and k (fused over M: mt 0..2 = Wq tile, 3..5 = Wk).
// Block tile 128(M) x 196(N), BK=16. Threads (28,8)=224, per-thread 16x7.
// Ws stored k-major [k][m] -> LDS.128 m-fragments. Xs [k][n] row-contig.
__global__ __launch_bounds__(224) void gemm_qk(
    const float* __restrict__ x,
    const float* __restrict__ Wq, const float* __restrict__ Wk,
    const float* __restrict__ qbeta, const float* __restrict__ qmean,
    const float* __restrict__ kbeta, const float* __restrict__ kmean)
{
    __shared__ float Ws[16*WS_S];
    __shared__ float Xs[16*XS_S];

    const int mt  = blockIdx.x;            // 0..5
    const int z   = blockIdx.y;            // t*BB+b
    const int sel = (mt >= 3) ? 1 : 0;     // 0 = q, 1 = k
    const int mbase = (mt - sel*3) * BMQ;

    const float* __restrict__ W = sel ? Wk : Wq;

    const int tx  = threadIdx.x;   // 0..27 (n)
    const int ty  = threadIdx.y;   // 0..7  (m group of 16)
    const int tid = ty*28 + tx;

    const float* __restrict__ xb = x + (size_t)z * CN;

    float acc[16][7];
    #pragma unroll
    for (int i = 0; i < 16; i++)
        #pragma unroll
        for (int j = 0; j < 7; j++) acc[i][j] = 0.f;

    float4 wpre[3], xpre[4];

    // prefetch first K chunk
    #pragma unroll
    for (int u = 0; u < 3; u++) {
        int idx = tid + u*224;
        if (idx < 512) {
            int row = idx >> 2, c4 = idx & 3;
            wpre[u] = *(const float4*)(W + (mbase + row)*CC + 4*c4);
        }
    }
    #pragma unroll
    for (int u = 0; u < 4; u++) {
        int idx = tid + u*224;
        if (idx < 784) {
            int c = idx/49, n4 = idx - 49*c;
            xpre[u] = *(const float4*)(xb + c*NN + 4*n4);
        }
    }

    for (int k0 = 0; k0 < CC; k0 += 16) {
        // commit prefetched tile (W transposed to k-major)
        #pragma unroll
        for (int u = 0; u < 3; u++) {
            int idx = tid + u*224;
            if (idx < 512) {
                int row = idx >> 2, c4 = idx & 3;
                Ws[(4*c4+0)*WS_S + row] = wpre[u].x;
                Ws[(4*c4+1)*WS_S + row] = wpre[u].y;
                Ws[(4*c4+2)*WS_S + row] = wpre[u].z;
                Ws[(4*c4+3)*WS_S + row] = wpre[u].w;
            }
        }
        #pragma unroll
        for (int u = 0; u < 4; u++) {
            int idx = tid + u*224;
            if (idx < 784) {
                int c = idx/49, n4 = idx - 49*c;
                *(float4*)(Xs + c*XS_S + 4*n4) = xpre[u];
            }
        }
        __syncthreads();

        const int k1 = k0 + 16;
        if (k1 < CC) {
            #pragma unroll
            for (int u = 0; u < 3; u++) {
                int idx = tid + u*224;
                if (idx < 512) {
                    int row = idx >> 2, c4 = idx & 3;
                    wpre[u] = *(const float4*)(W + (mbase + row)*CC + k1 + 4*c4);
                }
            }
            #pragma unroll
            for (int u = 0; u < 4; u++) {
                int idx = tid + u*224;
                if (idx < 784) {
                    int c = idx/49, n4 = idx - 49*c;
                    xpre[u] = *(const float4*)(xb + (k1 + c)*NN + 4*n4);
                }
            }
        }

        #pragma unroll 4
        for (int kk = 0; kk < 16; kk++) {
            float xv[7];
            #pragma unroll
            for (int j = 0; j < 7; j++) xv[j] = Xs[kk*XS_S + tx + 28*j];
            float wvf[16];
            const float4* wp4 = (const float4*)(Ws + kk*WS_S + ty*16);
            #pragma unroll
            for (int u = 0; u < 4; u++) {
                float4 wv = wp4[u];
                wvf[4*u+0] = wv.x; wvf[4*u+1] = wv.y;
                wvf[4*u+2] = wv.z; wvf[4*u+3] = wv.w;
            }
            #pragma unroll
            for (int i = 0; i < 16; i++)
                #pragma unroll
                for (int j = 0; j < 7; j++)
                    acc[i][j] = fmaf(wvf[i], xv[j], acc[i][j]);
        }
        __syncthreads();
    }

    const float* __restrict__ scl  = g_scale + sel*CC;
    const float* __restrict__ mean = sel ? kmean : qmean;
    const float* __restrict__ beta = sel ? kbeta : qbeta;
    float* __restrict__ outp = g_pre + (size_t)sel*TBCN + (size_t)z*CN;
    #pragma unroll
    for (int i = 0; i < 16; i++) {
        int ch = mbase + ty*16 + i;
        float sc = scl[ch], mu = mean[ch], be = beta[ch];
        #pragma unroll
        for (int j = 0; j < 7; j++) {
            int n = tx + 28*j;
            outp[ch*NN + n] = (acc[i][j] - mu)*sc + be;
        }
    }
}

// ---------------------------------------------------------------------------
// LIF over T for q and k pre-activations -> binary spikes (u8), float4-wide
__global__ void lif_qk()
{
    int i = blockIdx.x*blockDim.x + threadIdx.x;
    if (i >= BCN/4) return;
    const float4* __restrict__ qp = (const float4*)g_pre;
    const float4* __restrict__ kp = (const float4*)(g_pre + (size_t)TBCN);
    uchar4* __restrict__ qs = (uchar4*)g_qs;
    uchar4* __restrict__ ks = (uchar4*)g_ks;

    float4 vq = make_float4(0.f,0.f,0.f,0.f);
    float4 vk = make_float4(0.f,0.f,0.f,0.f);
    #pragma unroll
    for (int t = 0; t < TT; t++) {
        size_t off = (size_t)t*(BCN/4) + i;
        float4 xq = qp[off];
        vq.x += (xq.x - vq.x)*0.5f; vq.y += (xq.y - vq.y)*0.5f;
        vq.z += (xq.z - vq.z)*0.5f; vq.w += (xq.w - vq.w)*0.5f;
        uchar4 s;
        s.x = vq.x >= 1.f; s.y = vq.y >= 1.f; s.z = vq.z >= 1.f; s.w = vq.w >= 1.f;
        qs[off] = s;
        if (s.x) vq.x = 0.f; if (s.y) vq.y = 0.f;
        if (s.z) vq.z = 0.f; if (s.w) vq.w = 0.f;

        float4 xk = kp[off];
        vk.x += (xk.x - vk.x)*0.5f; vk.y += (xk.y - vk.y)*0.5f;
        vk.z += (xk.z - vk.z)*0.5f; vk.w += (xk.w - vk.w)*0.5f;
        uchar4 sk;
        sk.x = vk.x >= 1.f; sk.y = vk.y >= 1.f; sk.z = vk.z >= 1.f; sk.w = vk.w >= 1.f;
        ks[off] = sk;
        if (sk.x) vk.x = 0.f; if (sk.y) vk.y = 0.f;
        if (sk.z) vk.z = 0.f; if (sk.w) vk.w = 0.f;
    }
}

// ---------------------------------------------------------------------------
// Per-head sum of q spikes (48 channels) + LIF over T -> attn mask (u8)
__global__ void attn_kernel()
{
    int idx = blockIdx.x*blockDim.x + threadIdx.x;
    if (idx >= BHN) return;
    int n = idx % NN;
    int h = (idx / NN) % NHEAD;
    int b = idx / (NN*NHEAD);

    float v = 0.f;
    #pragma unroll
    for (int t = 0; t < TT; t++) {
        const unsigned char* __restrict__ p =
            g_qs + ((size_t)(t*BB + b)*CC + h*DHD)*NN + n;
        int s = 0;
        #pragma unroll
        for (int i2 = 0; i2 < DHD; i2++) s += p[(size_t)i2*NN];
        float sf = (float)s;
        v = v + (sf - v)*0.5f;
        unsigned char a = (v >= 1.0f) ? 1 : 0;
        g_attn[((size_t)(t*BB + b)*NHEAD + h)*NN + n] = a;
        if (a) v = 0.f;
    }
}

// ---------------------------------------------------------------------------
// GEMM Wp @ (attn & k) + bias, BN epilogue. Same skeleton as gemm_qk;
// operand built on the fly from binary spike masks.
__global__ __launch_bounds__(224) void gemm_p(
    const float* __restrict__ Wp, const float* __restrict__ bp,
    const float* __restrict__ pbeta, const float* __restrict__ pmean)
{
    __shared__ float Ws[16*WS_S];
    __shared__ float Xs[16*XS_S];

    const int mt    = blockIdx.x;       // 0..2
    const int z     = blockIdx.y;
    const int mbase = mt * BMQ;
    const float* __restrict__ scl = g_scale + 2*CC;

    const int tx  = threadIdx.x;
    const int ty  = threadIdx.y;
    const int tid = ty*28 + tx;

    const unsigned char* __restrict__ kb = g_ks   + (size_t)z*CN;
    const unsigned char* __restrict__ ab = g_attn + (size_t)z*NHEAD*NN;

    float acc[16][7];
    #pragma unroll
    for (int i = 0; i < 16; i++)
        #pragma unroll
        for (int j = 0; j < 7; j++) acc[i][j] = 0.f;

    float4 wpre[3], xpre[4];

    #pragma unroll
    for (int u = 0; u < 3; u++) {
        int idx = tid + u*224;
        if (idx < 512) {
            int row = idx >> 2, c4 = idx & 3;
            wpre[u] = *(const float4*)(Wp + (mbase + row)*CC + 4*c4);
        }
    }
    #pragma unroll
    for (int u = 0; u < 4; u++) {
        int idx = tid + u*224;
        if (idx < 784) {
            int c = idx/49, n = 4*(idx - 49*c);
            uchar4 kv = *(const uchar4*)(kb + c*NN + n);
            uchar4 av = *(const uchar4*)(ab + (c/DHD)*NN + n);
            xpre[u] = make_float4((kv.x & av.x) ? 1.f : 0.f,
                                  (kv.y & av.y) ? 1.f : 0.f,
                                  (kv.z & av.z) ? 1.f : 0.f,
                                  (kv.w & av.w) ? 1.f : 0.f);
        }
    }

    for (int k0 = 0; k0 < CC; k0 += 16) {
        #pragma unroll
        for (int u = 0; u < 3; u++) {
            int idx = tid + u*224;
            if (idx < 512) {
                int row = idx >> 2, c4 = idx & 3;
                Ws[(4*c4+0)*WS_S + row] = wpre[u].x;
                Ws[(4*c4+1)*WS_S + row] = wpre[u].y;
                Ws[(4*c4+2)*WS_S + row] = wpre[u].z;
                Ws[(4*c4+3)*WS_S + row] = wpre[u].w;
            }
        }
        #pragma unroll
        for (int u = 0; u < 4; u++) {
            int idx = tid + u*224;
            if (idx < 784) {
                int c = idx/49, n4 = idx - 49*c;
                *(float4*)(Xs + c*XS_S + 4*n4) = xpre[u];
            }
        }
        __syncthreads();

        const int k1 = k0 + 16;
        if (k1 < CC) {
            #pragma unroll
            for (int u = 0; u < 3; u++) {
                int idx = tid + u*224;
                if (idx < 512) {
                    int row = idx >> 2, c4 = idx & 3;
                    wpre[u] = *(const float4*)(Wp + (mbase + row)*CC + k1 + 4*c4);
                }
            }
            #pragma unroll
            for (int u = 0; u < 4; u++) {
                int idx = tid + u*224;
                if (idx < 784) {
                    int c = idx/49, n = 4*(idx - 49*c);
                    int cg = k1 + c;
                    uchar4 kv = *(const uchar4*)(kb + cg*NN + n);
                    uchar4 av = *(const uchar4*)(ab + (cg/DHD)*NN + n);
                    xpre[u] = make_float4((kv.x & av.x) ? 1.f : 0.f,
                                          (kv.y & av.y) ? 1.f : 0.f,
                                          (kv.z & av.z) ? 1.f : 0.f,
                                          (kv.w & av.w) ? 1.f : 0.f);
                }
            }
        }

        #pragma unroll 4
        for (int kk = 0; kk < 16; kk++) {
            float xv[7];
            #pragma unroll
            for (int j = 0; j < 7; j++) xv[j] = Xs[kk*XS_S + tx + 28*j];
            float wvf[16];
            const float4* wp4 = (const float4*)(Ws + kk*WS_S + ty*16);
            #pragma unroll
            for (int u = 0; u < 4; u++) {
                float4 wv = wp4[u];
                wvf[4*u+0] = wv.x; wvf[4*u+1] = wv.y;
                wvf[4*u+2] = wv.z; wvf[4*u+3] = wv.w;
            }
            #pragma unroll
            for (int i = 0; i < 16; i++)
                #pragma unroll
                for (int j = 0; j < 7; j++)
                    acc[i][j] = fmaf(wvf[i], xv[j], acc[i][j]);
        }
        __syncthreads();
    }

    float* __restrict__ outp = g_pre + (size_t)z*CN;   // reuse q region
    #pragma unroll
    for (int i = 0; i < 16; i++) {
        int ch = mbase + ty*16 + i;
        float sc = scl[ch], mu = pmean[ch], be = pbeta[ch], bv = bp[ch];
        #pragma unroll
        for (int j = 0; j < 7; j++) {
            int n = tx + 28*j;
            float tmp = acc[i][j] + bv;          // conv bias first (match ref)
            outp[ch*NN + n] = (tmp - mu)*sc + be;
        }
    }
}

// ---------------------------------------------------------------------------
// Final LIF over T -> binary output (float 0/1), float4-wide
__global__ void lif_out(float* __restrict__ out)
{
    int i = blockIdx.x*blockDim.x + threadIdx.x;
    if (i >= BCN/4) return;
    const float4* __restrict__ pp = (const float4*)g_pre;
    float4* __restrict__ op = (float4*)out;
    float4 v = make_float4(0.f,0.f,0.f,0.f);
    #pragma unroll
    for (int t = 0; t < TT; t++) {
        size_t off = (size_t)t*(BCN/4) + i;
        float4 xp = pp[off];
        v.x += (xp.x - v.x)*0.5f; v.y += (xp.y - v.y)*0.5f;
        v.z += (xp.z - v.z)*0.5f; v.w += (xp.w - v.w)*0.5f;
        float4 s;
        s.x = (v.x >= 1.f) ? 1.f : 0.f; s.y = (v.y >= 1.f) ? 1.f : 0.f;
        s.z = (v.z >= 1.f) ? 1.f : 0.f; s.w = (v.w >= 1.f) ? 1.f : 0.f;
        op[off] = s;
        if (s.x != 0.f) v.x = 0.f; if (s.y != 0.f) v.y = 0.f;
        if (s.z != 0.f) v.z = 0.f; if (s.w != 0.f) v.w = 0.f;
    }
}

// ---------------------------------------------------------------------------
extern "C" void kernel_launch(void* const* d_in, const int* in_sizes, int n_in,
                              void* d_out, int out_size)
{
    const float* x   = (const float*)d_in[0];
    const float* Wq  = (const float*)d_in[1];
    const float* qg  = (const float*)d_in[2];
    const float* qb  = (const float*)d_in[3];
    const float* qm  = (const float*)d_in[4];
    const float* qv  = (const float*)d_in[5];
    const float* Wk  = (const float*)d_in[6];
    const float* kg  = (const float*)d_in[7];
    const float* kb  = (const float*)d_in[8];
    const float* km  = (const float*)d_in[9];
    const float* kv  = (const float*)d_in[10];
    const float* Wp  = (const float*)d_in[11];
    const float* bp  = (const float*)d_in[12];
    const float* pg  = (const float*)d_in[13];
    const float* pb  = (const float*)d_in[14];
    const float* pm  = (const float*)d_in[15];
    const float* pv  = (const float*)d_in[16];
    float* out = (float*)d_out;

    bn_precompute<<<1, CC>>>(qg, qv, kg, kv, pg, pv);
    gemm_qk<<<dim3(6, TT*BB), dim3(28, 8)>>>(x, Wq, Wk, qb, qm, kb, km);
    lif_qk<<<(BCN/4 + 255)/256, 256>>>();
    attn_kernel<<<(BHN + 255)/256, 256>>>();
    gemm_p<<<dim3(3, TT*BB), dim3(28, 8)>>>(Wp, bp, pb, pm);
    lif_out<<<(BCN/4 + 255)/256, 256>>>(out);
}

// round 5
// speedup vs baseline: 1.4785x; 1.4312x over previous
#include <cuda_runtime.h>
#include <cstdint>
#include <math.h>

// Problem constants
#define TT    4
#define BB    64
#define CC    384
#define NN    196
#define NP    200             // padded N (rows 196..199 zeroed)
#define NHEAD 8
#define DHD   48
#define CN    (CC*NN)          // 75264
#define BCN   (BB*CC*NN)       // 4816896
#define TBCN  (TT*BCN)         // 19267584
#define BHN   (BB*NHEAD*NN)    // 100352
#define ZTOT  (TT*BB)          // 256

// SMEM tile geometry: BK=16, row stride 20 floats (80B) for conflict-free frags
#define KS     20
#define A_BYTES (128*KS*4)     // 10240
#define B_BYTES (NP*KS*4)      // 16000
// qk stage: Ahi, Alo, Bhi, Blo
#define QK_ALO  10240
#define QK_BHI  20480
#define QK_BLO  36480
#define QK_STG  52480
#define SMEM_QK (2*QK_STG)     // 104960
// p stage: Ahi, Alo, B
#define P_ALO   10240
#define P_B     20480
#define P_STG   36480
#define SMEM_P  (2*P_STG)      // 72960

// Scratch (allocation-free: __device__ globals)
__device__ float         g_pre[2u*TBCN];
__device__ float         g_xt [ZTOT*NP*CC];   // exact fp32, padded
__device__ float         g_xhi[ZTOT*NP*CC];
__device__ float         g_xlo[ZTOT*NP*CC];
__device__ float         g_yt [ZTOT*NP*CC];   // {0,1}, padded
__device__ float         g_whi[3*CC*CC];      // [sel][m][k], sel: 0=q,1=k,2=p
__device__ float         g_wlo[3*CC*CC];
__device__ unsigned char g_qs[TBCN];
__device__ unsigned char g_ks[TBCN];
__device__ unsigned char g_attn[(size_t)TT*BHN];
__device__ float         g_scale[3*CC];

// ---------------------------------------------------------------------------
// helpers
// ---------------------------------------------------------------------------
__device__ __forceinline__ uint32_t smem_u32(const void* p) {
    uint32_t a;
    asm("{ .reg .u64 t; cvta.to.shared.u64 t, %1; cvt.u32.u64 %0, t; }"
        : "=r"(a) : "l"(p));
    return a;
}
__device__ __forceinline__ float tf32r(float a) {
    uint32_t r;
    asm("cvt.rna.tf32.f32 %0, %1;" : "=r"(r) : "f"(a));
    return __uint_as_float(r);
}
__device__ __forceinline__ void cp16(uint32_t s, const void* g) {
    asm volatile("cp.async.cg.shared.global [%0], [%1], 16;"
                 :: "r"(s), "l"(g) : "memory");
}
#define CP_COMMIT() asm volatile("cp.async.commit_group;" ::: "memory")
#define CP_WAIT(n)  asm volatile("cp.async.wait_group %0;" :: "n"(n) : "memory")

__device__ __forceinline__ void mma8(float* d, const uint32_t* a,
                                     uint32_t b0, uint32_t b1) {
    asm volatile(
        "mma.sync.aligned.m16n8k8.row.col.f32.tf32.tf32.f32 "
        "{%0,%1,%2,%3}, {%4,%5,%6,%7}, {%8,%9}, {%0,%1,%2,%3};"
        : "+f"(d[0]), "+f"(d[1]), "+f"(d[2]), "+f"(d[3])
        : "r"(a[0]), "r"(a[1]), "r"(a[2]), "r"(a[3]), "r"(b0), "r"(b1));
}

// ---------------------------------------------------------------------------
__global__ void bn_precompute(const float* __restrict__ qg, const float* __restrict__ qv,
                              const float* __restrict__ kg, const float* __restrict__ kv,
                              const float* __restrict__ pg, const float* __restrict__ pv)
{
    int c = threadIdx.x;
    if (c < CC) {
        g_scale[c]        = qg[c] / sqrtf(qv[c] + 1e-5f);
        g_scale[CC + c]   = kg[c] / sqrtf(kv[c] + 1e-5f);
        g_scale[2*CC + c] = pg[c] / sqrtf(pv[c] + 1e-5f);
    }
}

// ---------------------------------------------------------------------------
__global__ void split_w(const float* __restrict__ Wq, const float* __restrict__ Wk,
                        const float* __restrict__ Wp)
{
    int i = blockIdx.x*256 + threadIdx.x;
    if (i >= 3*CC*CC) return;
    int sel = i / (CC*CC);
    int r   = i - sel*(CC*CC);
    const float* src = (sel == 0) ? Wq : (sel == 1 ? Wk : Wp);
    float w = src[r];
    float h = tf32r(w);
    g_whi[i] = h;
    g_wlo[i] = tf32r(w - h);
}

// ---------------------------------------------------------------------------
// Transpose + tf32 split: x[z][c][n] -> g_xt/g_xhi/g_xlo [z][n][c], pad rows.
__global__ void transpose_split_x(const float* __restrict__ x)
{
    __shared__ float S[32][33];
    const int z = blockIdx.x, ct = blockIdx.y, nt = blockIdx.z;
    const int tx = threadIdx.x, ty = threadIdx.y;
    #pragma unroll
    for (int u = 0; u < 4; u++) {
        int c = ct*32 + ty + u*8;
        int n = nt*32 + tx;
        if (n < NN) S[ty + u*8][tx] = x[((size_t)z*CC + c)*NN + n];
    }
    __syncthreads();
    const int c = ct*32 + tx;
    #pragma unroll
    for (int u = 0; u < 4; u++) {
        int n = nt*32 + ty + u*8;
        if (n >= NP) continue;
        size_t o = ((size_t)z*NP + n)*CC + c;
        if (n < NN) {
            float v = S[tx][ty + u*8];
            float h = tf32r(v);
            g_xt[o]  = v;
            g_xhi[o] = h;
            g_xlo[o] = tf32r(v - h);
        } else {
            g_xt[o] = 0.f; g_xhi[o] = 0.f; g_xlo[o] = 0.f;
        }
    }
}

// ---------------------------------------------------------------------------
// yT[z][n][c] = (k_spike & attn) in {0,1}, padded rows zeroed.
__global__ void build_yt()
{
    __shared__ unsigned char S[32][33];
    const int z = blockIdx.x, ct = blockIdx.y, nt = blockIdx.z;
    const int tx = threadIdx.x, ty = threadIdx.y;
    #pragma unroll
    for (int u = 0; u < 4; u++) {
        int c = ct*32 + ty + u*8;
        int n = nt*32 + tx;
        if (n < NN) S[ty + u*8][tx] = g_ks[((size_t)z*CC + c)*NN + n];
    }
    __syncthreads();
    const int c = ct*32 + tx;
    const int h = c / DHD;
    #pragma unroll
    for (int u = 0; u < 4; u++) {
        int n = nt*32 + ty + u*8;
        if (n >= NP) continue;
        float v = 0.f;
        if (n < NN) {
            unsigned char a = g_attn[((size_t)z*NHEAD + h)*NN + n];
            v = (S[tx][ty + u*8] & a) ? 1.0f : 0.0f;
        }
        g_yt[((size_t)z*NP + n)*CC + c] = v;
    }
}

// ---------------------------------------------------------------------------
// tf32 mma.sync GEMM for q & k (3-term split). Grid (6, 256).
// Block: M=128 x N=200 (25 n-tiles), K staged 16, cp.async double buffered.
// Warp w owns rows [w*16, w*16+16), all 25 n-tiles: acc[25][4].
__global__ __launch_bounds__(256, 1) void gemm_qk_mma(
    const float* __restrict__ qbeta, const float* __restrict__ qmean,
    const float* __restrict__ kbeta, const float* __restrict__ kmean)
{
    extern __shared__ char sm[];
    const int mt = blockIdx.x, z = blockIdx.y;
    const int sel = (mt >= 3) ? 1 : 0;
    const int mbase = (mt - sel*3) * 128;
    const int tid = threadIdx.x, wid = tid >> 5, lid = tid & 31;
    const uint32_t sb = smem_u32(sm);

    const float* __restrict__ whiP = g_whi + (size_t)sel*CC*CC + (size_t)mbase*CC;
    const float* __restrict__ wloP = g_wlo + (size_t)sel*CC*CC + (size_t)mbase*CC;
    const float* __restrict__ bhiP = g_xhi + (size_t)z*NP*CC;
    const float* __restrict__ bloP = g_xlo + (size_t)z*NP*CC;

    float acc[100];
    #pragma unroll
    for (int i = 0; i < 100; i++) acc[i] = 0.f;

    // stage loader
    auto load_stage = [&](int buf, int kof) {
        uint32_t sa = sb + buf*QK_STG;
        #pragma unroll
        for (int u = 0; u < 2; u++) {
            int idx = tid + u*256;          // 0..511
            int row = idx >> 2, c4 = idx & 3;
            cp16(sa + row*80 + c4*16,          whiP + (size_t)row*CC + kof + c4*4);
            cp16(sa + QK_ALO + row*80 + c4*16, wloP + (size_t)row*CC + kof + c4*4);
        }
        #pragma unroll
        for (int u = 0; u < 4; u++) {
            int idx = tid + u*256;
            if (idx < 800) {
                int row = idx >> 2, c4 = idx & 3;
                cp16(sa + QK_BHI + row*80 + c4*16, bhiP + (size_t)row*CC + kof + c4*4);
                cp16(sa + QK_BLO + row*80 + c4*16, bloP + (size_t)row*CC + kof + c4*4);
            }
        }
    };

    load_stage(0, 0);
    CP_COMMIT();

    const int r = lid >> 2, cq = lid & 3;

    for (int kt = 0; kt < 24; kt++) {
        if (kt + 1 < 24) { load_stage((kt+1) & 1, (kt+1)*16); CP_COMMIT(); CP_WAIT(1); }
        else             { CP_WAIT(0); }
        __syncthreads();

        const char* st = sm + (kt & 1)*QK_STG;
        const uint32_t* Ahi = (const uint32_t*)(st);
        const uint32_t* Alo = (const uint32_t*)(st + QK_ALO);
        const uint32_t* Bhi = (const uint32_t*)(st + QK_BHI);
        const uint32_t* Blo = (const uint32_t*)(st + QK_BLO);

        #pragma unroll
        for (int k8 = 0; k8 < 2; k8++) {
            const int kb = k8*8;
            uint32_t ah[4], al[4];
            int ab = (wid*16 + r)*KS + kb + cq;
            ah[0] = Ahi[ab];        ah[1] = Ahi[ab + 8*KS];
            ah[2] = Ahi[ab + 4];    ah[3] = Ahi[ab + 8*KS + 4];
            al[0] = Alo[ab];        al[1] = Alo[ab + 8*KS];
            al[2] = Alo[ab + 4];    al[3] = Alo[ab + 8*KS + 4];
            #pragma unroll
            for (int nt = 0; nt < 25; nt++) {
                int nb = (nt*8 + r)*KS + kb + cq;
                uint32_t bh0 = Bhi[nb], bh1 = Bhi[nb + 4];
                uint32_t bl0 = Blo[nb], bl1 = Blo[nb + 4];
                mma8(acc + nt*4, ah, bh0, bh1);
                mma8(acc + nt*4, al, bh0, bh1);
                mma8(acc + nt*4, ah, bl0, bl1);
            }
        }
        __syncthreads();
    }

    // BN epilogue
    const int ch0 = mbase + wid*16 + r, ch1 = ch0 + 8;
    const float sc0 = g_scale[sel*CC + ch0], sc1 = g_scale[sel*CC + ch1];
    const float* meanp = sel ? kmean : qmean;
    const float* betap = sel ? kbeta : qbeta;
    const float mu0 = meanp[ch0], mu1 = meanp[ch1];
    const float be0 = betap[ch0], be1 = betap[ch1];
    float* __restrict__ o0 = g_pre + (size_t)sel*TBCN + (size_t)z*CN + (size_t)ch0*NN;
    float* __restrict__ o1 = g_pre + (size_t)sel*TBCN + (size_t)z*CN + (size_t)ch1*NN;
    #pragma unroll
    for (int nt = 0; nt < 25; nt++) {
        int n = nt*8 + 2*cq;
        if (n < NN) {
            float2 v0, v1;
            v0.x = (acc[nt*4+0] - mu0)*sc0 + be0;
            v0.y = (acc[nt*4+1] - mu0)*sc0 + be0;
            v1.x = (acc[nt*4+2] - mu1)*sc1 + be1;
            v1.y = (acc[nt*4+3] - mu1)*sc1 + be1;
            *(float2*)(o0 + n) = v0;
            *(float2*)(o1 + n) = v1;
        }
    }
}

// ---------------------------------------------------------------------------
// tf32 mma.sync GEMM for projection (2-term split; B exact {0,1}). Grid (3,256).
__global__ __launch_bounds__(256, 1) void gemm_p_mma(
    const float* __restrict__ bp,
    const float* __restrict__ pbeta, const float* __restrict__ pmean)
{
    extern __shared__ char sm[];
    const int mt = blockIdx.x, z = blockIdx.y;
    const int mbase = mt * 128;
    const int tid = threadIdx.x, wid = tid >> 5, lid = tid & 31;
    const uint32_t sb = smem_u32(sm);

    const float* __restrict__ whiP = g_whi + (size_t)2*CC*CC + (size_t)mbase*CC;
    const float* __restrict__ wloP = g_wlo + (size_t)2*CC*CC + (size_t)mbase*CC;
    const float* __restrict__ bP   = g_yt + (size_t)z*NP*CC;

    float acc[100];
    #pragma unroll
    for (int i = 0; i < 100; i++) acc[i] = 0.f;

    auto load_stage = [&](int buf, int kof) {
        uint32_t sa = sb + buf*P_STG;
        #pragma unroll
        for (int u = 0; u < 2; u++) {
            int idx = tid + u*256;
            int row = idx >> 2, c4 = idx & 3;
            cp16(sa + row*80 + c4*16,         whiP + (size_t)row*CC + kof + c4*4);
            cp16(sa + P_ALO + row*80 + c4*16, wloP + (size_t)row*CC + kof + c4*4);
        }
        #pragma unroll
        for (int u = 0; u < 4; u++) {
            int idx = tid + u*256;
            if (idx < 800) {
                int row = idx >> 2, c4 = idx & 3;
                cp16(sa + P_B + row*80 + c4*16, bP + (size_t)row*CC + kof + c4*4);
            }
        }
    };

    load_stage(0, 0);
    CP_COMMIT();

    const int r = lid >> 2, cq = lid & 3;

    for (int kt = 0; kt < 24; kt++) {
        if (kt + 1 < 24) { load_stage((kt+1) & 1, (kt+1)*16); CP_COMMIT(); CP_WAIT(1); }
        else             { CP_WAIT(0); }
        __syncthreads();

        const char* st = sm + (kt & 1)*P_STG;
        const uint32_t* Ahi = (const uint32_t*)(st);
        const uint32_t* Alo = (const uint32_t*)(st + P_ALO);
        const uint32_t* Bs  = (const uint32_t*)(st + P_B);

        #pragma unroll
        for (int k8 = 0; k8 < 2; k8++) {
            const int kb = k8*8;
            uint32_t ah[4], al[4];
            int ab = (wid*16 + r)*KS + kb + cq;
            ah[0] = Ahi[ab];        ah[1] = Ahi[ab + 8*KS];
            ah[2] = Ahi[ab + 4];    ah[3] = Ahi[ab + 8*KS + 4];
            al[0] = Alo[ab];        al[1] = Alo[ab + 8*KS];
            al[2] = Alo[ab + 4];    al[3] = Alo[ab + 8*KS + 4];
            #pragma unroll
            for (int nt = 0; nt < 25; nt++) {
                int nb = (nt*8 + r)*KS + kb + cq;
                uint32_t b0 = Bs[nb], b1 = Bs[nb + 4];
                mma8(acc + nt*4, ah, b0, b1);
                mma8(acc + nt*4, al, b0, b1);
            }
        }
        __syncthreads();
    }

    const int ch0 = mbase + wid*16 + r, ch1 = ch0 + 8;
    const float sc0 = g_scale[2*CC + ch0], sc1 = g_scale[2*CC + ch1];
    const float mu0 = pmean[ch0], mu1 = pmean[ch1];
    const float be0 = pbeta[ch0], be1 = pbeta[ch1];
    const float bv0 = bp[ch0],    bv1 = bp[ch1];
    float* __restrict__ o0 = g_pre + (size_t)z*CN + (size_t)ch0*NN;
    float* __restrict__ o1 = g_pre + (size_t)z*CN + (size_t)ch1*NN;
    #pragma unroll
    for (int nt = 0; nt < 25; nt++) {
        int n = nt*8 + 2*cq;
        if (n < NN) {
            float2 v0, v1;
            v0.x = ((acc[nt*4+0] + bv0) - mu0)*sc0 + be0;
            v0.y = ((acc[nt*4+1] + bv0) - mu0)*sc0 + be0;
            v1.x = ((acc[nt*4+2] + bv1) - mu1)*sc1 + be1;
            v1.y = ((acc[nt*4+3] + bv1) - mu1)*sc1 + be1;
            *(float2*)(o0 + n) = v0;
            *(float2*)(o1 + n) = v1;
        }
    }
}

// ---------------------------------------------------------------------------
// LIF for q,k with exact fp32 repair for near-threshold chains.
__global__ void lif_qk(const float* __restrict__ Wq, const float* __restrict__ Wk,
                       const float* __restrict__ qbeta, const float* __restrict__ qmean,
                       const float* __restrict__ kbeta, const float* __restrict__ kmean)
{
    int i = blockIdx.x*blockDim.x + threadIdx.x;
    if (i >= BCN) return;
    const int b  = i / CN;
    const int rr = i - b*CN;
    const int ch = rr / NN;
    const int n  = rr - ch*NN;

    #pragma unroll
    for (int qk = 0; qk < 2; qk++) {
        const size_t base = (size_t)qk * TBCN;
        float v = 0.f, mn = 1e9f;
        unsigned char* __restrict__ sp = qk ? g_ks : g_qs;
        #pragma unroll
        for (int t = 0; t < TT; t++) {
            float xv = g_pre[base + (size_t)t*BCN + i];
            v += (xv - v)*0.5f;
            float d = fabsf(v - 1.f);
            if (d < mn) mn = d;
            unsigned char s = (v >= 1.f) ? 1 : 0;
            sp[(size_t)t*BCN + i] = s;
            if (s) v = 0.f;
        }
        if (mn < 2.5e-4f) {  // exact fp32 repair
            const float sc = g_scale[qk*CC + ch];
            const float mu = (qk ? kmean : qmean)[ch];
            const float be = (qk ? kbeta : qbeta)[ch];
            const float* __restrict__ wr = (qk ? Wk : Wq) + (size_t)ch*CC;
            v = 0.f;
            for (int t = 0; t < TT; t++) {
                const float* __restrict__ xr =
                    g_xt + ((size_t)(t*BB + b)*NP + n)*CC;
                float accv = 0.f;
                for (int c = 0; c < CC; c++) accv = fmaf(wr[c], xr[c], accv);
                float pre = (accv - mu)*sc + be;
                v += (pre - v)*0.5f;
                unsigned char s = (v >= 1.f) ? 1 : 0;
                sp[(size_t)t*BCN + i] = s;
                if (s) v = 0.f;
            }
        }
    }
}

// ---------------------------------------------------------------------------
__global__ void attn_kernel()
{
    int idx = blockIdx.x*blockDim.x + threadIdx.x;
    if (idx >= BHN) return;
    int n = idx % NN;
    int h = (idx / NN) % NHEAD;
    int b = idx / (NN*NHEAD);

    float v = 0.f;
    #pragma unroll
    for (int t = 0; t < TT; t++) {
        const unsigned char* __restrict__ p =
            g_qs + ((size_t)(t*BB + b)*CC + h*DHD)*NN + n;
        int s = 0;
        #pragma unroll
        for (int i2 = 0; i2 < DHD; i2++) s += p[(size_t)i2*NN];
        float sf = (float)s;
        v = v + (sf - v)*0.5f;
        unsigned char a = (v >= 1.0f) ? 1 : 0;
        g_attn[((size_t)(t*BB + b)*NHEAD + h)*NN + n] = a;
        if (a) v = 0.f;
    }
}

// ---------------------------------------------------------------------------
__global__ void lif_out(float* __restrict__ out,
                        const float* __restrict__ Wp, const float* __restrict__ bp,
                        const float* __restrict__ pbeta, const float* __restrict__ pmean)
{
    int i = blockIdx.x*blockDim.x + threadIdx.x;
    if (i >= BCN) return;
    const int b  = i / CN;
    const int rr = i - b*CN;
    const int ch = rr / NN;
    const int n  = rr - ch*NN;

    float v = 0.f, mn = 1e9f;
    float sv[TT];
    #pragma unroll
    for (int t = 0; t < TT; t++) {
        float xv = g_pre[(size_t)t*BCN + i];
        v += (xv - v)*0.5f;
        float d = fabsf(v - 1.f);
        if (d < mn) mn = d;
        float s = (v >= 1.f) ? 1.f : 0.f;
        sv[t] = s;
        if (s != 0.f) v = 0.f;
    }
    if (mn < 2.5e-4f) {
        const float sc = g_scale[2*CC + ch];
        const float mu = pmean[ch], be = pbeta[ch], bv = bp[ch];
        const float* __restrict__ wr = Wp + (size_t)ch*CC;
        v = 0.f;
        for (int t = 0; t < TT; t++) {
            const float* __restrict__ yr = g_yt + ((size_t)(t*BB + b)*NP + n)*CC;
            float accv = 0.f;
            for (int c = 0; c < CC; c++) accv = fmaf(wr[c], yr[c], accv);
            float pre = ((accv + bv) - mu)*sc + be;
            v += (pre - v)*0.5f;
            float s = (v >= 1.f) ? 1.f : 0.f;
            sv[t] = s;
            if (s != 0.f) v = 0.f;
        }
    }
    #pragma unroll
    for (int t = 0; t < TT; t++) out[(size_t)t*BCN + i] = sv[t];
}

// ---------------------------------------------------------------------------
extern "C" void kernel_launch(void* const* d_in, const int* in_sizes, int n_in,
                              void* d_out, int out_size)
{
    const float* x   = (const float*)d_in[0];
    const float* Wq  = (const float*)d_in[1];
    const float* qg  = (const float*)d_in[2];
    const float* qb  = (const float*)d_in[3];
    const float* qm  = (const float*)d_in[4];
    const float* qv  = (const float*)d_in[5];
    const float* Wk  = (const float*)d_in[6];
    const float* kg  = (const float*)d_in[7];
    const float* kb  = (const float*)d_in[8];
    const float* km  = (const float*)d_in[9];
    const float* kv  = (const float*)d_in[10];
    const float* Wp  = (const float*)d_in[11];
    const float* bp  = (const float*)d_in[12];
    const float* pg  = (const float*)d_in[13];
    const float* pb  = (const float*)d_in[14];
    const float* pm  = (const float*)d_in[15];
    const float* pv  = (const float*)d_in[16];
    float* out = (float*)d_out;

    static bool attr_done = false;
    if (!attr_done) {
        cudaFuncSetAttribute(gemm_qk_mma, cudaFuncAttributeMaxDynamicSharedMemorySize, SMEM_QK);
        cudaFuncSetAttribute(gemm_p_mma,  cudaFuncAttributeMaxDynamicSharedMemorySize, SMEM_P);
        attr_done = true;
    }

    bn_precompute<<<1, CC>>>(qg, qv, kg, kv, pg, pv);
    split_w<<<(3*CC*CC + 255)/256, 256>>>(Wq, Wk, Wp);
    transpose_split_x<<<dim3(ZTOT, 12, 7), dim3(32, 8)>>>(x);
    gemm_qk_mma<<<dim3(6, ZTOT), 256, SMEM_QK>>>(qb, qm, kb, km);
    lif_qk<<<(BCN + 255)/256, 256>>>(Wq, Wk, qb, qm, kb, km);
    attn_kernel<<<(BHN + 255)/256, 256>>>();
    build_yt<<<dim3(ZTOT, 12, 7), dim3(32, 8)>>>();
    gemm_p_mma<<<dim3(3, ZTOT), 256, SMEM_P>>>(bp, pb, pm);
    lif_out<<<(BCN + 255)/256, 256>>>(out, Wp, bp, pb, pm);
}

// round 6
// speedup vs baseline: 2.0203x; 1.3664x over previous
#include <cuda_runtime.h>
#include <cuda_bf16.h>
#include <cstdint>
#include <math.h>

// Problem constants
#define TT    4
#define BB    64
#define CC    384
#define NN    196
#define NP    208             // padded N (mult of 16; rows 196..207 zeroed)
#define NHEAD 8
#define DHD   48
#define CN    (CC*NN)          // 75264
#define BCN   (BB*CC*NN)       // 4816896
#define TBCN  (TT*BCN)         // 19267584
#define BHN   (BB*NHEAD*NN)    // 100352
#define ZTOT  (TT*BB)          // 256

// SMEM: BK=32 bf16 per stage, rows padded to 40 bf16 (80B) -> conflict-free
// qk stage: Ahi(128x40) Alo Bhi(208x40) Blo
#define QK_ALO  10240
#define QK_BHI  20480
#define QK_BLO  37120
#define QK_STG  53760
#define SMEM_QK (2*QK_STG)     // 107520
// p stage: Ahi Alo B
#define P_B     20480
#define P_STG   37120
#define SMEM_P  (2*P_STG)      // 74240

#define REPAIR_TH 1e-3f

// Scratch (allocation-free: __device__ globals)
__device__ float          g_pre[2u*TBCN];
__device__ float          g_xt [(size_t)ZTOT*NP*CC];   // exact fp32 (repair)
__device__ __nv_bfloat16  g_xhi[(size_t)ZTOT*NP*CC];
__device__ __nv_bfloat16  g_xlo[(size_t)ZTOT*NP*CC];
__device__ __nv_bfloat16  g_yt [(size_t)ZTOT*NP*CC];   // {0,1}
__device__ __nv_bfloat16  g_whi[3*CC*CC];
__device__ __nv_bfloat16  g_wlo[3*CC*CC];
__device__ unsigned char  g_qs[TBCN];
__device__ unsigned char  g_ks[TBCN];
__device__ unsigned char  g_attn[(size_t)TT*BHN];
__device__ float          g_scale[3*CC];

// ---------------------------------------------------------------------------
__device__ __forceinline__ uint32_t smem_u32(const void* p) {
    uint32_t a;
    asm("{ .reg .u64 t; cvta.to.shared.u64 t, %1; cvt.u32.u64 %0, t; }"
        : "=r"(a) : "l"(p));
    return a;
}
__device__ __forceinline__ void cp16(uint32_t s, const void* g) {
    asm volatile("cp.async.cg.shared.global [%0], [%1], 16;"
                 :: "r"(s), "l"(g) : "memory");
}
#define CP_COMMIT() asm volatile("cp.async.commit_group;" ::: "memory")
#define CP_WAIT(n)  asm volatile("cp.async.wait_group %0;" :: "n"(n) : "memory")

__device__ __forceinline__ void mma_bf16(float* d, const uint32_t* a,
                                         uint32_t b0, uint32_t b1) {
    asm volatile(
        "mma.sync.aligned.m16n8k16.row.col.f32.bf16.bf16.f32 "
        "{%0,%1,%2,%3}, {%4,%5,%6,%7}, {%8,%9}, {%0,%1,%2,%3};"
        : "+f"(d[0]), "+f"(d[1]), "+f"(d[2]), "+f"(d[3])
        : "r"(a[0]), "r"(a[1]), "r"(a[2]), "r"(a[3]), "r"(b0), "r"(b1));
}

// ---------------------------------------------------------------------------
__global__ void bn_precompute(const float* __restrict__ qg, const float* __restrict__ qv,
                              const float* __restrict__ kg, const float* __restrict__ kv,
                              const float* __restrict__ pg, const float* __restrict__ pv)
{
    int c = threadIdx.x;
    if (c < CC) {
        g_scale[c]        = qg[c] / sqrtf(qv[c] + 1e-5f);
        g_scale[CC + c]   = kg[c] / sqrtf(kv[c] + 1e-5f);
        g_scale[2*CC + c] = pg[c] / sqrtf(pv[c] + 1e-5f);
    }
}

// ---------------------------------------------------------------------------
__global__ void split_w(const float* __restrict__ Wq, const float* __restrict__ Wk,
                        const float* __restrict__ Wp)
{
    int i = blockIdx.x*256 + threadIdx.x;
    if (i >= 3*CC*CC) return;
    int sel = i / (CC*CC);
    int r   = i - sel*(CC*CC);
    const float* src = (sel == 0) ? Wq : (sel == 1 ? Wk : Wp);
    float w = src[r];
    __nv_bfloat16 h = __float2bfloat16(w);
    g_whi[i] = h;
    g_wlo[i] = __float2bfloat16(w - __bfloat162float(h));
}

// ---------------------------------------------------------------------------
// x[z][c][n] -> g_xt (fp32) / g_xhi / g_xlo (bf16 split), layout [z][n][c].
__global__ void transpose_split_x(const float* __restrict__ x)
{
    __shared__ float S[32][33];
    const int z = blockIdx.x, ct = blockIdx.y, nt = blockIdx.z;
    const int tx = threadIdx.x, ty = threadIdx.y;
    #pragma unroll
    for (int u = 0; u < 4; u++) {
        int c = ct*32 + ty + u*8;
        int n = nt*32 + tx;
        if (n < NN) S[ty + u*8][tx] = x[((size_t)z*CC + c)*NN + n];
    }
    __syncthreads();
    const int c = ct*32 + tx;
    #pragma unroll
    for (int u = 0; u < 4; u++) {
        int n = nt*32 + ty + u*8;
        if (n >= NP) continue;
        size_t o = ((size_t)z*NP + n)*CC + c;
        float v = (n < NN) ? S[tx][ty + u*8] : 0.f;
        __nv_bfloat16 h = __float2bfloat16(v);
        g_xt[o]  = v;
        g_xhi[o] = h;
        g_xlo[o] = __float2bfloat16(v - __bfloat162float(h));
    }
}

// ---------------------------------------------------------------------------
// g_yt[z][n][c] = (k_spike & attn) in {0,1} bf16, padded rows zeroed.
__global__ void build_yt()
{
    __shared__ unsigned char S[32][33];
    const int z = blockIdx.x, ct = blockIdx.y, nt = blockIdx.z;
    const int tx = threadIdx.x, ty = threadIdx.y;
    #pragma unroll
    for (int u = 0; u < 4; u++) {
        int c = ct*32 + ty + u*8;
        int n = nt*32 + tx;
        if (n < NN) S[ty + u*8][tx] = g_ks[((size_t)z*CC + c)*NN + n];
    }
    __syncthreads();
    const int c = ct*32 + tx;
    const int h = c / DHD;
    #pragma unroll
    for (int u = 0; u < 4; u++) {
        int n = nt*32 + ty + u*8;
        if (n >= NP) continue;
        float v = 0.f;
        if (n < NN) {
            unsigned char a = g_attn[((size_t)z*NHEAD + h)*NN + n];
            v = (S[tx][ty + u*8] & a) ? 1.0f : 0.0f;
        }
        g_yt[((size_t)z*NP + n)*CC + c] = __float2bfloat16(v);
    }
}

// ---------------------------------------------------------------------------
// bf16 2-term-split GEMM for q & k (3 mma terms). Grid (6, 256).
// Block 128M x 208N; warps 4(M)x2(N): warp = 2 m16-tiles x 13 n8-tiles.
// BK=32 (2 k16 steps), cp.async double buffered.
__global__ __launch_bounds__(256, 1) void gemm_qk_mma(
    const float* __restrict__ qbeta, const float* __restrict__ qmean,
    const float* __restrict__ kbeta, const float* __restrict__ kmean)
{
    extern __shared__ char sm[];
    const int mt = blockIdx.x, z = blockIdx.y;
    const int sel = (mt >= 3) ? 1 : 0;
    const int mbase = (mt - sel*3) * 128;
    const int tid = threadIdx.x, wid = tid >> 5, lid = tid & 31;
    const int wm = wid & 3, wn = wid >> 2;          // 4 M-groups x 2 N-groups
    const int r = lid >> 2, cq = lid & 3;
    const uint32_t sb = smem_u32(sm);

    const __nv_bfloat16* __restrict__ whiP = g_whi + (size_t)sel*CC*CC + (size_t)mbase*CC;
    const __nv_bfloat16* __restrict__ wloP = g_wlo + (size_t)sel*CC*CC + (size_t)mbase*CC;
    const __nv_bfloat16* __restrict__ bhiP = g_xhi + (size_t)z*NP*CC;
    const __nv_bfloat16* __restrict__ bloP = g_xlo + (size_t)z*NP*CC;

    float acc[104];
    #pragma unroll
    for (int i = 0; i < 104; i++) acc[i] = 0.f;

    auto load_stage = [&](int buf, int kof) {
        uint32_t sa = sb + buf*QK_STG;
        #pragma unroll
        for (int u = 0; u < 4; u++) {            // A: 1024 cp16
            int idx = tid + u*256;
            int plane = idx >> 9;
            int row   = (idx >> 2) & 127;
            int c4    = idx & 3;
            const __nv_bfloat16* g = (plane ? wloP : whiP) + (size_t)row*CC + kof + c4*8;
            cp16(sa + plane*QK_ALO + row*80 + c4*16, g);
        }
        #pragma unroll
        for (int u = 0; u < 7; u++) {            // B: 1664 cp16
            int idx = tid + u*256;
            if (idx < 1664) {
                int plane = (idx >= 832);
                int r2 = plane ? idx - 832 : idx;
                int row = r2 >> 2, c4 = r2 & 3;
                const __nv_bfloat16* g = (plane ? bloP : bhiP) + (size_t)row*CC + kof + c4*8;
                cp16(sa + QK_BHI + plane*16640 + row*80 + c4*16, g);
            }
        }
    };

    load_stage(0, 0);
    CP_COMMIT();

    for (int kt = 0; kt < 12; kt++) {
        if (kt + 1 < 12) { load_stage((kt+1) & 1, (kt+1)*32); CP_COMMIT(); CP_WAIT(1); }
        else             { CP_WAIT(0); }
        __syncthreads();

        const uint32_t* st  = (const uint32_t*)(sm + (kt & 1)*QK_STG);
        const uint32_t* Ahi = st;
        const uint32_t* Alo = st + QK_ALO/4;
        const uint32_t* Bhi = st + QK_BHI/4;
        const uint32_t* Blo = st + QK_BLO/4;

        #pragma unroll
        for (int ks = 0; ks < 2; ks++) {
            const int kp = ks*8;
            uint32_t ah[2][4], al[2][4];
            #pragma unroll
            for (int m = 0; m < 2; m++) {
                int base = (wm*32 + m*16 + r)*20 + kp + cq;
                ah[m][0] = Ahi[base];       ah[m][1] = Ahi[base + 160];
                ah[m][2] = Ahi[base + 4];   ah[m][3] = Ahi[base + 164];
                al[m][0] = Alo[base];       al[m][1] = Alo[base + 160];
                al[m][2] = Alo[base + 4];   al[m][3] = Alo[base + 164];
            }
            #pragma unroll
            for (int nt = 0; nt < 13; nt++) {
                int nbase = (wn*104 + nt*8 + r)*20 + kp + cq;
                uint32_t bh0 = Bhi[nbase], bh1 = Bhi[nbase + 4];
                uint32_t bl0 = Blo[nbase], bl1 = Blo[nbase + 4];
                #pragma unroll
                for (int m = 0; m < 2; m++) {
                    float* d = acc + (m*13 + nt)*4;
                    mma_bf16(d, ah[m], bh0, bh1);
                    mma_bf16(d, al[m], bh0, bh1);
                    mma_bf16(d, ah[m], bl0, bl1);
                }
            }
        }
        __syncthreads();
    }

    // BN epilogue
    const float* meanp = sel ? kmean : qmean;
    const float* betap = sel ? kbeta : qbeta;
    #pragma unroll
    for (int m = 0; m < 2; m++) {
        int ch0 = mbase + wm*32 + m*16 + r, ch1 = ch0 + 8;
        float sc0 = g_scale[sel*CC + ch0], sc1 = g_scale[sel*CC + ch1];
        float mu0 = meanp[ch0], mu1 = meanp[ch1];
        float be0 = betap[ch0], be1 = betap[ch1];
        float* __restrict__ o0 = g_pre + (size_t)sel*TBCN + (size_t)z*CN + (size_t)ch0*NN;
        float* __restrict__ o1 = g_pre + (size_t)sel*TBCN + (size_t)z*CN + (size_t)ch1*NN;
        #pragma unroll
        for (int nt = 0; nt < 13; nt++) {
            int n = wn*104 + nt*8 + 2*cq;
            if (n < NN) {
                const float* d = acc + (m*13 + nt)*4;
                float2 v0, v1;
                v0.x = (d[0] - mu0)*sc0 + be0;
                v0.y = (d[1] - mu0)*sc0 + be0;
                v1.x = (d[2] - mu1)*sc1 + be1;
                v1.y = (d[3] - mu1)*sc1 + be1;
                *(float2*)(o0 + n) = v0;
                *(float2*)(o1 + n) = v1;
            }
        }
    }
}

// ---------------------------------------------------------------------------
// Projection GEMM: A = Wp 2-term split, B = yt exact {0,1}. Grid (3, 256).
__global__ __launch_bounds__(256, 1) void gemm_p_mma(
    const float* __restrict__ bp,
    const float* __restrict__ pbeta, const float* __restrict__ pmean)
{
    extern __shared__ char sm[];
    const int mt = blockIdx.x, z = blockIdx.y;
    const int mbase = mt * 128;
    const int tid = threadIdx.x, wid = tid >> 5, lid = tid & 31;
    const int wm = wid & 3, wn = wid >> 2;
    const int r = lid >> 2, cq = lid & 3;
    const uint32_t sb = smem_u32(sm);

    const __nv_bfloat16* __restrict__ whiP = g_whi + (size_t)2*CC*CC + (size_t)mbase*CC;
    const __nv_bfloat16* __restrict__ wloP = g_wlo + (size_t)2*CC*CC + (size_t)mbase*CC;
    const __nv_bfloat16* __restrict__ bP   = g_yt + (size_t)z*NP*CC;

    float acc[104];
    #pragma unroll
    for (int i = 0; i < 104; i++) acc[i] = 0.f;

    auto load_stage = [&](int buf, int kof) {
        uint32_t sa = sb + buf*P_STG;
        #pragma unroll
        for (int u = 0; u < 4; u++) {
            int idx = tid + u*256;
            int plane = idx >> 9;
            int row   = (idx >> 2) & 127;
            int c4    = idx & 3;
            const __nv_bfloat16* g = (plane ? wloP : whiP) + (size_t)row*CC + kof + c4*8;
            cp16(sa + plane*QK_ALO + row*80 + c4*16, g);
        }
        #pragma unroll
        for (int u = 0; u < 4; u++) {            // B: 832 cp16
            int idx = tid + u*256;
            if (idx < 832) {
                int row = idx >> 2, c4 = idx & 3;
                cp16(sa + P_B + row*80 + c4*16, bP + (size_t)row*CC + kof + c4*8);
            }
        }
    };

    load_stage(0, 0);
    CP_COMMIT();

    for (int kt = 0; kt < 12; kt++) {
        if (kt + 1 < 12) { load_stage((kt+1) & 1, (kt+1)*32); CP_COMMIT(); CP_WAIT(1); }
        else             { CP_WAIT(0); }
        __syncthreads();

        const uint32_t* st  = (const uint32_t*)(sm + (kt & 1)*P_STG);
        const uint32_t* Ahi = st;
        const uint32_t* Alo = st + QK_ALO/4;
        const uint32_t* Bs  = st + P_B/4;

        #pragma unroll
        for (int ks = 0; ks < 2; ks++) {
            const int kp = ks*8;
            uint32_t ah[2][4], al[2][4];
            #pragma unroll
            for (int m = 0; m < 2; m++) {
                int base = (wm*32 + m*16 + r)*20 + kp + cq;
                ah[m][0] = Ahi[base];       ah[m][1] = Ahi[base + 160];
                ah[m][2] = Ahi[base + 4];   ah[m][3] = Ahi[base + 164];
                al[m][0] = Alo[base];       al[m][1] = Alo[base + 160];
                al[m][2] = Alo[base + 4];   al[m][3] = Alo[base + 164];
            }
            #pragma unroll
            for (int nt = 0; nt < 13; nt++) {
                int nbase = (wn*104 + nt*8 + r)*20 + kp + cq;
                uint32_t b0 = Bs[nbase], b1 = Bs[nbase + 4];
                #pragma unroll
                for (int m = 0; m < 2; m++) {
                    float* d = acc + (m*13 + nt)*4;
                    mma_bf16(d, ah[m], b0, b1);
                    mma_bf16(d, al[m], b0, b1);
                }
            }
        }
        __syncthreads();
    }

    #pragma unroll
    for (int m = 0; m < 2; m++) {
        int ch0 = mbase + wm*32 + m*16 + r, ch1 = ch0 + 8;
        float sc0 = g_scale[2*CC + ch0], sc1 = g_scale[2*CC + ch1];
        float mu0 = pmean[ch0], mu1 = pmean[ch1];
        float be0 = pbeta[ch0], be1 = pbeta[ch1];
        float bv0 = bp[ch0],    bv1 = bp[ch1];
        float* __restrict__ o0 = g_pre + (size_t)z*CN + (size_t)ch0*NN;
        float* __restrict__ o1 = g_pre + (size_t)z*CN + (size_t)ch1*NN;
        #pragma unroll
        for (int nt = 0; nt < 13; nt++) {
            int n = wn*104 + nt*8 + 2*cq;
            if (n < NN) {
                const float* d = acc + (m*13 + nt)*4;
                float2 v0, v1;
                v0.x = ((d[0] + bv0) - mu0)*sc0 + be0;
                v0.y = ((d[1] + bv0) - mu0)*sc0 + be0;
                v1.x = ((d[2] + bv1) - mu1)*sc1 + be1;
                v1.y = ((d[3] + bv1) - mu1)*sc1 + be1;
                *(float2*)(o0 + n) = v0;
                *(float2*)(o1 + n) = v1;
            }
        }
    }
}

// ---------------------------------------------------------------------------
// LIF for q,k with exact fp32 repair for near-threshold chains.
__global__ void lif_qk(const float* __restrict__ Wq, const float* __restrict__ Wk,
                       const float* __restrict__ qbeta, const float* __restrict__ qmean,
                       const float* __restrict__ kbeta, const float* __restrict__ kmean)
{
    int i = blockIdx.x*blockDim.x + threadIdx.x;
    if (i >= BCN) return;
    const int b  = i / CN;
    const int rr = i - b*CN;
    const int ch = rr / NN;
    const int n  = rr - ch*NN;

    #pragma unroll
    for (int qk = 0; qk < 2; qk++) {
        const size_t base = (size_t)qk * TBCN;
        float v = 0.f, mn = 1e9f;
        unsigned char* __restrict__ sp = qk ? g_ks : g_qs;
        #pragma unroll
        for (int t = 0; t < TT; t++) {
            float xv = g_pre[base + (size_t)t*BCN + i];
            v += (xv - v)*0.5f;
            float d = fabsf(v - 1.f);
            if (d < mn) mn = d;
            unsigned char s = (v >= 1.f) ? 1 : 0;
            sp[(size_t)t*BCN + i] = s;
            if (s) v = 0.f;
        }
        if (mn < REPAIR_TH) {     // exact fp32 repair
            const float sc = g_scale[qk*CC + ch];
            const float mu = (qk ? kmean : qmean)[ch];
            const float be = (qk ? kbeta : qbeta)[ch];
            const float* __restrict__ wr = (qk ? Wk : Wq) + (size_t)ch*CC;
            v = 0.f;
            for (int t = 0; t < TT; t++) {
                const float* __restrict__ xr =
                    g_xt + ((size_t)(t*BB + b)*NP + n)*CC;
                float accv = 0.f;
                for (int c = 0; c < CC; c++) accv = fmaf(wr[c], xr[c], accv);
                float pre = (accv - mu)*sc + be;
                v += (pre - v)*0.5f;
                unsigned char s = (v >= 1.f) ? 1 : 0;
                sp[(size_t)t*BCN + i] = s;
                if (s) v = 0.f;
            }
        }
    }
}

// ---------------------------------------------------------------------------
__global__ void attn_kernel()
{
    int idx = blockIdx.x*blockDim.x + threadIdx.x;
    if (idx >= BHN) return;
    int n = idx % NN;
    int h = (idx / NN) % NHEAD;
    int b = idx / (NN*NHEAD);

    float v = 0.f;
    #pragma unroll
    for (int t = 0; t < TT; t++) {
        const unsigned char* __restrict__ p =
            g_qs + ((size_t)(t*BB + b)*CC + h*DHD)*NN + n;
        int s = 0;
        #pragma unroll
        for (int i2 = 0; i2 < DHD; i2++) s += p[(size_t)i2*NN];
        float sf = (float)s;
        v = v + (sf - v)*0.5f;
        unsigned char a = (v >= 1.0f) ? 1 : 0;
        g_attn[((size_t)(t*BB + b)*NHEAD + h)*NN + n] = a;
        if (a) v = 0.f;
    }
}

// ---------------------------------------------------------------------------
__global__ void lif_out(float* __restrict__ out,
                        const float* __restrict__ Wp, const float* __restrict__ bp,
                        const float* __restrict__ pbeta, const float* __restrict__ pmean)
{
    int i = blockIdx.x*blockDim.x + threadIdx.x;
    if (i >= BCN) return;
    const int b  = i / CN;
    const int rr = i - b*CN;
    const int ch = rr / NN;
    const int n  = rr - ch*NN;

    float v = 0.f, mn = 1e9f;
    float sv[TT];
    #pragma unroll
    for (int t = 0; t < TT; t++) {
        float xv = g_pre[(size_t)t*BCN + i];
        v += (xv - v)*0.5f;
        float d = fabsf(v - 1.f);
        if (d < mn) mn = d;
        float s = (v >= 1.f) ? 1.f : 0.f;
        sv[t] = s;
        if (s != 0.f) v = 0.f;
    }
    if (mn < REPAIR_TH) {
        const float sc = g_scale[2*CC + ch];
        const float mu = pmean[ch], be = pbeta[ch], bv = bp[ch];
        const float* __restrict__ wr = Wp + (size_t)ch*CC;
        v = 0.f;
        for (int t = 0; t < TT; t++) {
            const __nv_bfloat16* __restrict__ yr =
                g_yt + ((size_t)(t*BB + b)*NP + n)*CC;
            float accv = 0.f;
            for (int c = 0; c < CC; c++)
                accv = fmaf(wr[c], __bfloat162float(yr[c]), accv);
            float pre = ((accv + bv) - mu)*sc + be;
            v += (pre - v)*0.5f;
            float s = (v >= 1.f) ? 1.f : 0.f;
            sv[t] = s;
            if (s != 0.f) v = 0.f;
        }
    }
    #pragma unroll
    for (int t = 0; t < TT; t++) out[(size_t)t*BCN + i] = sv[t];
}

// ---------------------------------------------------------------------------
extern "C" void kernel_launch(void* const* d_in, const int* in_sizes, int n_in,
                              void* d_out, int out_size)
{
    const float* x   = (const float*)d_in[0];
    const float* Wq  = (const float*)d_in[1];
    const float* qg  = (const float*)d_in[2];
    const float* qb  = (const float*)d_in[3];
    const float* qm  = (const float*)d_in[4];
    const float* qv  = (const float*)d_in[5];
    const float* Wk  = (const float*)d_in[6];
    const float* kg  = (const float*)d_in[7];
    const float* kb  = (const float*)d_in[8];
    const float* km  = (const float*)d_in[9];
    const float* kv  = (const float*)d_in[10];
    const float* Wp  = (const float*)d_in[11];
    const float* bp  = (const float*)d_in[12];
    const float* pg  = (const float*)d_in[13];
    const float* pb  = (const float*)d_in[14];
    const float* pm  = (const float*)d_in[15];
    const float* pv  = (const float*)d_in[16];
    float* out = (float*)d_out;

    static bool attr_done = false;
    if (!attr_done) {
        cudaFuncSetAttribute(gemm_qk_mma, cudaFuncAttributeMaxDynamicSharedMemorySize, SMEM_QK);
        cudaFuncSetAttribute(gemm_p_mma,  cudaFuncAttributeMaxDynamicSharedMemorySize, SMEM_P);
        attr_done = true;
    }

    bn_precompute<<<1, CC>>>(qg, qv, kg, kv, pg, pv);
    split_w<<<(3*CC*CC + 255)/256, 256>>>(Wq, Wk, Wp);
    transpose_split_x<<<dim3(ZTOT, 12, 7), dim3(32, 8)>>>(x);
    gemm_qk_mma<<<dim3(6, ZTOT), 256, SMEM_QK>>>(qb, qm, kb, km);
    lif_qk<<<(BCN + 255)/256, 256>>>(Wq, Wk, qb, qm, kb, km);
    attn_kernel<<<(BHN + 255)/256, 256>>>();
    build_yt<<<dim3(ZTOT, 12, 7), dim3(32, 8)>>>();
    gemm_p_mma<<<dim3(3, ZTOT), 256, SMEM_P>>>(bp, pb, pm);
    lif_out<<<(BCN + 255)/256, 256>>>(out, Wp, bp, pb, pm);
}